// round 2
// baseline (speedup 1.0000x reference)
#include <cuda_runtime.h>
#include <math.h>
#include <stdint.h>

// Problem constants
#define BATCH 4
#define SEQ   2048
#define DEMB  512
#define NHEAD 8
#define DHEAD 64
#define DMODL 512              // NHEAD*DHEAD
#define MROWS (BATCH*SEQ)      // 8192

// ---------------- scratch (device globals; no allocation) ----------------
__device__ float g_z [MROWS * DEMB];   // x + pe
__device__ float g_q [MROWS * DMODL];  // [B,H,S,Dh]
__device__ float g_k [MROWS * DMODL];
__device__ float g_v [MROWS * DMODL];
__device__ float g_h [MROWS * DMODL];  // attention out, [B,S,H*Dh]
__device__ float g_z2[MROWS * DEMB];   // z + h@Wo + bo
__device__ float g_f [MROWS * DEMB];   // leaky(z2@W1+b1)

// ---------------- helpers ----------------
__device__ __forceinline__ uint32_t f2tf32(float x) {
    uint32_t r;
    asm("cvt.rna.tf32.f32 %0, %1;" : "=r"(r) : "f"(x));
    return r;
}

__device__ __forceinline__ void mma_tf32(float c[4],
                                         const uint32_t a[4],
                                         const uint32_t b[2]) {
    asm volatile(
        "mma.sync.aligned.m16n8k8.row.col.f32.tf32.tf32.f32 "
        "{%0,%1,%2,%3}, {%4,%5,%6,%7}, {%8,%9}, {%0,%1,%2,%3};"
        : "+f"(c[0]), "+f"(c[1]), "+f"(c[2]), "+f"(c[3])
        : "r"(a[0]), "r"(a[1]), "r"(a[2]), "r"(a[3]),
          "r"(b[0]), "r"(b[1]));
}

// ---------------- 1) positional encoding add ----------------
__global__ void pe_add_kernel(const float* __restrict__ x, float* __restrict__ z) {
    int idx = blockIdx.x * blockDim.x + threadIdx.x;   // over MROWS*DEMB
    if (idx >= MROWS * DEMB) return;
    int d = idx & (DEMB - 1);
    int s = (idx >> 9) & (SEQ - 1);
    int i2 = (d >> 1) * 2;
    float divv = expf(-(float)i2 * (9.210340371976184f / 512.0f));
    float ang = (float)s * divv;
    float pe = (d & 1) ? cosf(ang) : sinf(ang);
    z[idx] = x[idx] + pe;
}

// ---------------- 2) tf32 tensor-core GEMM ----------------
// C[M,N] = A[M,K] @ W[K,N] + bias, M=8192, N=512, K=512
// Block tile 128x128, k-chunk 32, 256 threads (8 warps, 2x4), warp tile 64x32.
// MODE 0: QKV head scatter; MODE 1: residual add; MODE 2: leaky relu.
#define GK 512
#define GN 512

template<int MODE>
__global__ __launch_bounds__(256)
void gemm_tc_kernel(const float* __restrict__ A, const float* __restrict__ W,
                    const float* __restrict__ bias, const float* __restrict__ resid,
                    float* __restrict__ C) {
    __shared__ uint32_t As[32][132];   // [k][m], padded
    __shared__ uint32_t Bs[32][132];   // [k][n], padded

    const int bm = blockIdx.y * 128;
    const int bn = blockIdx.x * 128;
    const int tid  = threadIdx.x;
    const int lane = tid & 31;
    const int wid  = tid >> 5;
    const int wm = (wid >> 2) * 64;    // 0 or 64
    const int wn = (wid & 3) * 32;     // 0..96
    const int lq = lane & 3;           // tid-in-group (k idx)
    const int lg = lane >> 2;          // group id (row/col idx)

    float acc[4][4][4];
#pragma unroll
    for (int i = 0; i < 4; i++)
#pragma unroll
        for (int j = 0; j < 4; j++)
#pragma unroll
            for (int r = 0; r < 4; r++) acc[i][j][r] = 0.0f;

    for (int k0 = 0; k0 < GK; k0 += 32) {
        // --- stage A tile (128 x 32), transposed into As[k][m], tf32 ---
#pragma unroll
        for (int i = 0; i < 4; i++) {
            int idx = tid * 4 + i;         // 0..1023 float4 slots
            int row = idx >> 3;            // 0..127
            int c4  = idx & 7;             // 0..7
            float4 a = *(const float4*)&A[(size_t)(bm + row) * GK + k0 + c4 * 4];
            As[c4 * 4 + 0][row] = f2tf32(a.x);
            As[c4 * 4 + 1][row] = f2tf32(a.y);
            As[c4 * 4 + 2][row] = f2tf32(a.z);
            As[c4 * 4 + 3][row] = f2tf32(a.w);
        }
        // --- stage B tile (32 x 128) into Bs[k][n], tf32 ---
#pragma unroll
        for (int i = 0; i < 4; i++) {
            int idx = tid * 4 + i;         // 0..1023
            int row = idx >> 5;            // 0..31  (k)
            int c4  = idx & 31;            // 0..31  (n float4)
            float4 w = *(const float4*)&W[(size_t)(k0 + row) * GN + bn + c4 * 4];
            uint4 u;
            u.x = f2tf32(w.x); u.y = f2tf32(w.y);
            u.z = f2tf32(w.z); u.w = f2tf32(w.w);
            *(uint4*)&Bs[row][c4 * 4] = u;
        }
        __syncthreads();

#pragma unroll
        for (int ks = 0; ks < 32; ks += 8) {
            uint32_t afrag[4][4];
            uint32_t bfrag[4][2];
#pragma unroll
            for (int mt = 0; mt < 4; mt++) {
                int mrow = wm + mt * 16 + lg;
                afrag[mt][0] = As[ks + lq][mrow];
                afrag[mt][1] = As[ks + lq][mrow + 8];
                afrag[mt][2] = As[ks + lq + 4][mrow];
                afrag[mt][3] = As[ks + lq + 4][mrow + 8];
            }
#pragma unroll
            for (int nt = 0; nt < 4; nt++) {
                int ncol = wn + nt * 8 + lg;
                bfrag[nt][0] = Bs[ks + lq][ncol];
                bfrag[nt][1] = Bs[ks + lq + 4][ncol];
            }
#pragma unroll
            for (int mt = 0; mt < 4; mt++)
#pragma unroll
                for (int nt = 0; nt < 4; nt++)
                    mma_tf32(acc[mt][nt], afrag[mt], bfrag[nt]);
        }
        __syncthreads();
    }

    // --- epilogue ---
#pragma unroll
    for (int mt = 0; mt < 4; mt++) {
#pragma unroll
        for (int nt = 0; nt < 4; nt++) {
#pragma unroll
            for (int half = 0; half < 2; half++) {   // c0/c1 then c2/c3
                int m = bm + wm + mt * 16 + lg + half * 8;
                int n = bn + wn + nt * 8 + 2 * lq;
                float v0 = acc[mt][nt][half * 2 + 0] + bias[n];
                float v1 = acc[mt][nt][half * 2 + 1] + bias[n + 1];
                if (MODE == 0) {
                    int b = m >> 11, s = m & (SEQ - 1);
                    int h = n >> 6,  dh = n & 63;
                    float2* p = (float2*)&g_q[0]; // placeholder type only
                    (void)p;
                    float2 val = make_float2(v0, v1);
                    *(float2*)&C[((((size_t)b * NHEAD + h) * SEQ + s) << 6) + dh] = val;
                } else if (MODE == 1) {
                    float2 r = *(const float2*)&resid[(size_t)m * GN + n];
                    *(float2*)&C[(size_t)m * GN + n] = make_float2(v0 + r.x, v1 + r.y);
                } else {
                    float2 val;
                    val.x = (v0 > 0.0f) ? v0 : 0.01f * v0;
                    val.y = (v1 > 0.0f) ? v1 : 0.01f * v1;
                    *(float2*)&C[(size_t)m * GN + n] = val;
                }
            }
        }
    }
}

// ---------------- 3) fused flash-style attention (fp32, spill-free) ----------------
// grid: (B*H, SEQ/128), 128 threads; each thread owns one query row.
// Keys processed in 64-wide smem tiles, scored in 16-wide register sub-chunks.
__global__ __launch_bounds__(128, 3)
void attn_kernel(const float* __restrict__ q, const float* __restrict__ k,
                 const float* __restrict__ v, float* __restrict__ hout) {
    __shared__ float Ksh[64 * 64];
    __shared__ float Vsh[64 * 64];

    int bh = blockIdx.x;                   // 0..31
    int qt = blockIdx.y;                   // 0..15
    int tid = threadIdx.x;                 // 0..127
    int qrow = qt * 128 + tid;

    const float* qp = q + ((size_t)bh * SEQ + qrow) * DHEAD;
    float qr[64];
#pragma unroll
    for (int d4 = 0; d4 < 16; d4++) {
        float4 t = *(const float4*)&qp[d4 * 4];
        qr[4 * d4 + 0] = t.x; qr[4 * d4 + 1] = t.y;
        qr[4 * d4 + 2] = t.z; qr[4 * d4 + 3] = t.w;
    }

    float o[64];
#pragma unroll
    for (int d = 0; d < 64; d++) o[d] = 0.0f;
    float mrun = -1e30f, lrun = 0.0f;
    const float scale = 0.125f;            // 1/sqrt(64)

    for (int kt = 0; kt < SEQ / 64; kt++) {
        const float4* kp = (const float4*)(k + ((size_t)bh * SEQ + kt * 64) * DHEAD);
        const float4* vp = (const float4*)(v + ((size_t)bh * SEQ + kt * 64) * DHEAD);
#pragma unroll
        for (int i = 0; i < 8; i++) {
            ((float4*)Ksh)[i * 128 + tid] = kp[i * 128 + tid];
            ((float4*)Vsh)[i * 128 + tid] = vp[i * 128 + tid];
        }
        __syncthreads();

#pragma unroll
        for (int sub = 0; sub < 4; sub++) {
            const int base = sub * 16;
            float sc[16];
            float tmax = mrun;
#pragma unroll
            for (int j = 0; j < 16; j++) {
                const float4* kr = (const float4*)&Ksh[(base + j) * 64];
                float s = 0.0f;
#pragma unroll
                for (int d4 = 0; d4 < 16; d4++) {
                    float4 kk = kr[d4];
                    s += qr[4 * d4 + 0] * kk.x + qr[4 * d4 + 1] * kk.y
                       + qr[4 * d4 + 2] * kk.z + qr[4 * d4 + 3] * kk.w;
                }
                s *= scale;
                sc[j] = s;
                tmax = fmaxf(tmax, s);
            }

            float corr = __expf(mrun - tmax);
            mrun = tmax;
            lrun *= corr;
#pragma unroll
            for (int d = 0; d < 64; d++) o[d] *= corr;

#pragma unroll
            for (int j = 0; j < 16; j++) {
                float p = __expf(sc[j] - mrun);
                lrun += p;
                const float4* vr = (const float4*)&Vsh[(base + j) * 64];
#pragma unroll
                for (int d4 = 0; d4 < 16; d4++) {
                    float4 vv = vr[d4];
                    o[4 * d4 + 0] += p * vv.x; o[4 * d4 + 1] += p * vv.y;
                    o[4 * d4 + 2] += p * vv.z; o[4 * d4 + 3] += p * vv.w;
                }
            }
        }
        __syncthreads();
    }

    float inv = 1.0f / lrun;
    int b = bh >> 3, h = bh & 7;
    float* op = hout + ((((size_t)b * SEQ + qrow) * NHEAD + h) << 6);
#pragma unroll
    for (int d4 = 0; d4 < 16; d4++) {
        float4 t;
        t.x = o[4 * d4 + 0] * inv; t.y = o[4 * d4 + 1] * inv;
        t.z = o[4 * d4 + 2] * inv; t.w = o[4 * d4 + 3] * inv;
        *(float4*)&op[d4 * 4] = t;
    }
}

// ---------------- launcher ----------------
extern "C" void kernel_launch(void* const* d_in, const int* in_sizes, int n_in,
                              void* d_out, int out_size) {
    const float* x  = (const float*)d_in[0];
    const float* Wq = (const float*)d_in[1];
    const float* bq = (const float*)d_in[2];
    const float* Wk = (const float*)d_in[3];
    const float* bk = (const float*)d_in[4];
    const float* Wv = (const float*)d_in[5];
    const float* bv = (const float*)d_in[6];
    const float* Wo = (const float*)d_in[7];
    const float* bo = (const float*)d_in[8];
    const float* W1 = (const float*)d_in[9];
    const float* b1 = (const float*)d_in[10];
    const float* W2 = (const float*)d_in[11];
    const float* b2 = (const float*)d_in[12];
    float* out = (float*)d_out;

    float *z, *q, *k, *v, *h, *z2, *f;
    cudaGetSymbolAddress((void**)&z,  g_z);
    cudaGetSymbolAddress((void**)&q,  g_q);
    cudaGetSymbolAddress((void**)&k,  g_k);
    cudaGetSymbolAddress((void**)&v,  g_v);
    cudaGetSymbolAddress((void**)&h,  g_h);
    cudaGetSymbolAddress((void**)&z2, g_z2);
    cudaGetSymbolAddress((void**)&f,  g_f);

    // 1) z = x + pe
    pe_add_kernel<<<(MROWS * DEMB) / 256, 256>>>(x, z);

    // 2) Q, K, V projections with head scatter (tf32 tensor cores)
    dim3 gg(GN / 128, MROWS / 128);   // (4, 64)
    gemm_tc_kernel<0><<<gg, 256>>>(z, Wq, bq, nullptr, q);
    gemm_tc_kernel<0><<<gg, 256>>>(z, Wk, bk, nullptr, k);
    gemm_tc_kernel<0><<<gg, 256>>>(z, Wv, bv, nullptr, v);

    // 3) attention
    attn_kernel<<<dim3(BATCH * NHEAD, SEQ / 128), 128>>>(q, k, v, h);

    // 4) out projection + residual
    gemm_tc_kernel<1><<<gg, 256>>>(h, Wo, bo, z, z2);

    // 5) FFN
    gemm_tc_kernel<2><<<gg, 256>>>(z2, W1, b1, nullptr, f);
    gemm_tc_kernel<2><<<gg, 256>>>(f,  W2, b2, nullptr, out);
}

// round 3
// speedup vs baseline: 4.7676x; 4.7676x over previous
#include <cuda_runtime.h>
#include <math.h>
#include <stdint.h>

// Problem constants
#define BATCH 4
#define SEQ   2048
#define DEMB  512
#define NHEAD 8
#define DHEAD 64
#define DMODL 512              // NHEAD*DHEAD
#define MROWS (BATCH*SEQ)      // 8192

// ---------------- scratch (device globals; no allocation) ----------------
__device__ float g_z [MROWS * DEMB];   // x + pe
__device__ float g_q [MROWS * DMODL];  // [B,H,S,Dh]
__device__ float g_k [MROWS * DMODL];
__device__ float g_v [MROWS * DMODL];
__device__ float g_h [MROWS * DMODL];  // attention out, [B,S,H*Dh]
__device__ float g_z2[MROWS * DEMB];   // z + h@Wo + bo
__device__ float g_f [MROWS * DEMB];   // leaky(z2@W1+b1)

// ---------------- helpers ----------------
__device__ __forceinline__ uint32_t f2tf32(float x) {
    uint32_t r;
    asm("cvt.rna.tf32.f32 %0, %1;" : "=r"(r) : "f"(x));
    return r;
}

__device__ __forceinline__ void mma_tf32(float c[4],
                                         const uint32_t a[4],
                                         const uint32_t b0, const uint32_t b1) {
    asm volatile(
        "mma.sync.aligned.m16n8k8.row.col.f32.tf32.tf32.f32 "
        "{%0,%1,%2,%3}, {%4,%5,%6,%7}, {%8,%9}, {%0,%1,%2,%3};"
        : "+f"(c[0]), "+f"(c[1]), "+f"(c[2]), "+f"(c[3])
        : "r"(a[0]), "r"(a[1]), "r"(a[2]), "r"(a[3]),
          "r"(b0), "r"(b1));
}

// ---------------- 1) positional encoding add ----------------
__global__ void pe_add_kernel(const float* __restrict__ x, float* __restrict__ z) {
    int idx = blockIdx.x * blockDim.x + threadIdx.x;   // over MROWS*DEMB
    if (idx >= MROWS * DEMB) return;
    int d = idx & (DEMB - 1);
    int s = (idx >> 9) & (SEQ - 1);
    int i2 = (d >> 1) * 2;
    float divv = expf(-(float)i2 * (9.210340371976184f / 512.0f));
    float ang = (float)s * divv;
    float pe = (d & 1) ? cosf(ang) : sinf(ang);
    z[idx] = x[idx] + pe;
}

// ---------------- 2) tf32 tensor-core GEMM ----------------
// C[M,N] = A[M,K] @ W[K,N] + bias, M=8192, N=512, K=512
// Block tile 128x128, k-chunk 32, 256 threads (8 warps, 2x4), warp tile 64x32.
// MODE 0: QKV head scatter; MODE 1: residual add; MODE 2: leaky relu.
#define GK 512
#define GN 512

template<int MODE>
__global__ __launch_bounds__(256)
void gemm_tc_kernel(const float* __restrict__ A, const float* __restrict__ W,
                    const float* __restrict__ bias, const float* __restrict__ resid,
                    float* __restrict__ C) {
    __shared__ uint32_t As[32][132];   // [k][m], padded
    __shared__ uint32_t Bs[32][132];   // [k][n], padded

    const int bm = blockIdx.y * 128;
    const int bn = blockIdx.x * 128;
    const int tid  = threadIdx.x;
    const int lane = tid & 31;
    const int wid  = tid >> 5;
    const int wm = (wid >> 2) * 64;    // 0 or 64
    const int wn = (wid & 3) * 32;     // 0..96
    const int lq = lane & 3;           // k idx within fragment
    const int lg = lane >> 2;          // row/col idx within fragment

    float acc[4][4][4];
#pragma unroll
    for (int i = 0; i < 4; i++)
#pragma unroll
        for (int j = 0; j < 4; j++)
#pragma unroll
            for (int r = 0; r < 4; r++) acc[i][j][r] = 0.0f;

    for (int k0 = 0; k0 < GK; k0 += 32) {
#pragma unroll
        for (int i = 0; i < 4; i++) {
            int idx = tid * 4 + i;
            int row = idx >> 3;
            int c4  = idx & 7;
            float4 a = *(const float4*)&A[(size_t)(bm + row) * GK + k0 + c4 * 4];
            As[c4 * 4 + 0][row] = f2tf32(a.x);
            As[c4 * 4 + 1][row] = f2tf32(a.y);
            As[c4 * 4 + 2][row] = f2tf32(a.z);
            As[c4 * 4 + 3][row] = f2tf32(a.w);
        }
#pragma unroll
        for (int i = 0; i < 4; i++) {
            int idx = tid * 4 + i;
            int row = idx >> 5;
            int c4  = idx & 31;
            float4 w = *(const float4*)&W[(size_t)(k0 + row) * GN + bn + c4 * 4];
            uint4 u;
            u.x = f2tf32(w.x); u.y = f2tf32(w.y);
            u.z = f2tf32(w.z); u.w = f2tf32(w.w);
            *(uint4*)&Bs[row][c4 * 4] = u;
        }
        __syncthreads();

#pragma unroll
        for (int ks = 0; ks < 32; ks += 8) {
            uint32_t afrag[4][4];
            uint32_t bfrag[4][2];
#pragma unroll
            for (int mt = 0; mt < 4; mt++) {
                int mrow = wm + mt * 16 + lg;
                afrag[mt][0] = As[ks + lq][mrow];
                afrag[mt][1] = As[ks + lq][mrow + 8];
                afrag[mt][2] = As[ks + lq + 4][mrow];
                afrag[mt][3] = As[ks + lq + 4][mrow + 8];
            }
#pragma unroll
            for (int nt = 0; nt < 4; nt++) {
                int ncol = wn + nt * 8 + lg;
                bfrag[nt][0] = Bs[ks + lq][ncol];
                bfrag[nt][1] = Bs[ks + lq + 4][ncol];
            }
#pragma unroll
            for (int mt = 0; mt < 4; mt++)
#pragma unroll
                for (int nt = 0; nt < 4; nt++)
                    mma_tf32(acc[mt][nt], afrag[mt], bfrag[nt][0], bfrag[nt][1]);
        }
        __syncthreads();
    }

#pragma unroll
    for (int mt = 0; mt < 4; mt++) {
#pragma unroll
        for (int nt = 0; nt < 4; nt++) {
#pragma unroll
            for (int half = 0; half < 2; half++) {
                int m = bm + wm + mt * 16 + lg + half * 8;
                int n = bn + wn + nt * 8 + 2 * lq;
                float v0 = acc[mt][nt][half * 2 + 0] + bias[n];
                float v1 = acc[mt][nt][half * 2 + 1] + bias[n + 1];
                if (MODE == 0) {
                    int b = m >> 11, s = m & (SEQ - 1);
                    int h = n >> 6,  dh = n & 63;
                    *(float2*)&C[((((size_t)b * NHEAD + h) * SEQ + s) << 6) + dh] =
                        make_float2(v0, v1);
                } else if (MODE == 1) {
                    float2 r = *(const float2*)&resid[(size_t)m * GN + n];
                    *(float2*)&C[(size_t)m * GN + n] = make_float2(v0 + r.x, v1 + r.y);
                } else {
                    float2 val;
                    val.x = (v0 > 0.0f) ? v0 : 0.01f * v0;
                    val.y = (v1 > 0.0f) ? v1 : 0.01f * v1;
                    *(float2*)&C[(size_t)m * GN + n] = val;
                }
            }
        }
    }
}

// ---------------- 3) tensor-core flash attention (tf32) ----------------
// grid (B*H=32, SEQ/128=16), 256 threads (8 warps).
// Warp w owns query rows [16w, 16w+16). Q frags in registers (scale folded in).
// Smem strides chosen for conflict-free fragment loads:
//   Ksh stride 68: b0=Ksh[key][dim] -> 4*lg+lq distinct
//   Vsh stride 72: b0=Vsh[key][dim] -> 8*lq+lg distinct
//   Psh stride 68: a0=Psh[row][key] -> 4*lg+lq distinct
#define KST 68
#define VST 72
#define PST 68

extern __shared__ uint32_t att_smem[];

__global__ __launch_bounds__(256)
void attn_tc_kernel(const float* __restrict__ q, const float* __restrict__ k,
                    const float* __restrict__ v, float* __restrict__ hout) {
    uint32_t* Ksh = att_smem;                 // 64*68
    uint32_t* Vsh = Ksh + 64 * KST;           // 64*72
    uint32_t* Psh = Vsh + 64 * VST;           // 128*68 (also Q staging)

    const int bh  = blockIdx.x;               // 0..31
    const int qt  = blockIdx.y;               // 0..15
    const int tid = threadIdx.x;
    const int lane = tid & 31;
    const int wid  = tid >> 5;                 // 0..7
    const int lq = lane & 3;
    const int lg = lane >> 2;
    const int wrow = wid * 16;

    // ---- stage Q (scaled) into Psh, then load fragments ----
    const float* qbase = q + ((size_t)bh * SEQ + qt * 128) * DHEAD;
#pragma unroll
    for (int i = 0; i < 8; i++) {
        int idx = i * 256 + tid;               // 0..2047 float4 slots
        int row = idx >> 4;
        int c4  = idx & 15;
        float4 t = *(const float4*)&qbase[row * DHEAD + c4 * 4];
        uint4 u;
        u.x = f2tf32(t.x * 0.125f); u.y = f2tf32(t.y * 0.125f);
        u.z = f2tf32(t.z * 0.125f); u.w = f2tf32(t.w * 0.125f);
        *(uint4*)&Psh[row * PST + c4 * 4] = u;
    }
    __syncthreads();

    uint32_t qfrag[8][4];
#pragma unroll
    for (int kc = 0; kc < 8; kc++) {
        qfrag[kc][0] = Psh[(wrow + lg)     * PST + kc * 8 + lq];
        qfrag[kc][1] = Psh[(wrow + lg + 8) * PST + kc * 8 + lq];
        qfrag[kc][2] = Psh[(wrow + lg)     * PST + kc * 8 + lq + 4];
        qfrag[kc][3] = Psh[(wrow + lg + 8) * PST + kc * 8 + lq + 4];
    }

    float oacc[8][4];
#pragma unroll
    for (int nt = 0; nt < 8; nt++)
#pragma unroll
        for (int r = 0; r < 4; r++) oacc[nt][r] = 0.0f;
    float mrun0 = -1e30f, mrun1 = -1e30f;
    float lrun0 = 0.0f,   lrun1 = 0.0f;

    const float* kb = k + (size_t)bh * SEQ * DHEAD;
    const float* vb = v + (size_t)bh * SEQ * DHEAD;

    for (int kt = 0; kt < SEQ / 64; kt++) {
        __syncthreads();   // protect Ksh/Vsh (prev tile) and Psh (Q stage / prev P)
        // ---- stage K, V tiles (64x64) as tf32 ----
#pragma unroll
        for (int i = 0; i < 4; i++) {
            int idx = i * 256 + tid;           // 0..1023 float4 slots
            int key = idx >> 4;
            int c4  = idx & 15;
            float4 kk = *(const float4*)&kb[(kt * 64 + key) * DHEAD + c4 * 4];
            uint4 uk;
            uk.x = f2tf32(kk.x); uk.y = f2tf32(kk.y);
            uk.z = f2tf32(kk.z); uk.w = f2tf32(kk.w);
            *(uint4*)&Ksh[key * KST + c4 * 4] = uk;
            float4 vv = *(const float4*)&vb[(kt * 64 + key) * DHEAD + c4 * 4];
            uint4 uv;
            uv.x = f2tf32(vv.x); uv.y = f2tf32(vv.y);
            uv.z = f2tf32(vv.z); uv.w = f2tf32(vv.w);
            *(uint4*)&Vsh[key * VST + c4 * 4] = uv;
        }
        __syncthreads();

        // ---- S = Q @ K^T  (S[16 x 64] per warp) ----
        float sacc[8][4];
#pragma unroll
        for (int nt = 0; nt < 8; nt++)
#pragma unroll
            for (int r = 0; r < 4; r++) sacc[nt][r] = 0.0f;
#pragma unroll
        for (int kc = 0; kc < 8; kc++) {
#pragma unroll
            for (int nt = 0; nt < 8; nt++) {
                uint32_t b0 = Ksh[(nt * 8 + lg) * KST + kc * 8 + lq];
                uint32_t b1 = Ksh[(nt * 8 + lg) * KST + kc * 8 + lq + 4];
                mma_tf32(sacc[nt], qfrag[kc], b0, b1);
            }
        }

        // ---- online softmax (rows r0 = wrow+lg, r1 = wrow+lg+8) ----
        float tmax0 = mrun0, tmax1 = mrun1;
#pragma unroll
        for (int nt = 0; nt < 8; nt++) {
            tmax0 = fmaxf(tmax0, fmaxf(sacc[nt][0], sacc[nt][1]));
            tmax1 = fmaxf(tmax1, fmaxf(sacc[nt][2], sacc[nt][3]));
        }
        tmax0 = fmaxf(tmax0, __shfl_xor_sync(0xffffffff, tmax0, 1));
        tmax0 = fmaxf(tmax0, __shfl_xor_sync(0xffffffff, tmax0, 2));
        tmax1 = fmaxf(tmax1, __shfl_xor_sync(0xffffffff, tmax1, 1));
        tmax1 = fmaxf(tmax1, __shfl_xor_sync(0xffffffff, tmax1, 2));

        float corr0 = __expf(mrun0 - tmax0);
        float corr1 = __expf(mrun1 - tmax1);
        mrun0 = tmax0; mrun1 = tmax1;
#pragma unroll
        for (int nt = 0; nt < 8; nt++) {
            oacc[nt][0] *= corr0; oacc[nt][1] *= corr0;
            oacc[nt][2] *= corr1; oacc[nt][3] *= corr1;
        }

        float ps0 = 0.0f, ps1 = 0.0f;
#pragma unroll
        for (int nt = 0; nt < 8; nt++) {
            float p0 = __expf(sacc[nt][0] - mrun0);
            float p1 = __expf(sacc[nt][1] - mrun0);
            float p2 = __expf(sacc[nt][2] - mrun1);
            float p3 = __expf(sacc[nt][3] - mrun1);
            ps0 += p0 + p1;
            ps1 += p2 + p3;
            int col = nt * 8 + 2 * lq;
            Psh[(wrow + lg)     * PST + col]     = f2tf32(p0);
            Psh[(wrow + lg)     * PST + col + 1] = f2tf32(p1);
            Psh[(wrow + lg + 8) * PST + col]     = f2tf32(p2);
            Psh[(wrow + lg + 8) * PST + col + 1] = f2tf32(p3);
        }
        ps0 += __shfl_xor_sync(0xffffffff, ps0, 1);
        ps0 += __shfl_xor_sync(0xffffffff, ps0, 2);
        ps1 += __shfl_xor_sync(0xffffffff, ps1, 1);
        ps1 += __shfl_xor_sync(0xffffffff, ps1, 2);
        lrun0 = lrun0 * corr0 + ps0;
        lrun1 = lrun1 * corr1 + ps1;

        __syncwarp();   // P rows are warp-private: warp-level sync suffices

        // ---- O += P @ V ----
#pragma unroll
        for (int kc = 0; kc < 8; kc++) {
            uint32_t a[4];
            a[0] = Psh[(wrow + lg)     * PST + kc * 8 + lq];
            a[1] = Psh[(wrow + lg + 8) * PST + kc * 8 + lq];
            a[2] = Psh[(wrow + lg)     * PST + kc * 8 + lq + 4];
            a[3] = Psh[(wrow + lg + 8) * PST + kc * 8 + lq + 4];
#pragma unroll
            for (int nt = 0; nt < 8; nt++) {
                uint32_t b0 = Vsh[(kc * 8 + lq)     * VST + nt * 8 + lg];
                uint32_t b1 = Vsh[(kc * 8 + lq + 4) * VST + nt * 8 + lg];
                mma_tf32(oacc[nt], a, b0, b1);
            }
        }
        __syncwarp();
    }

    // ---- epilogue: normalize and write h [B,S,H*Dh] ----
    float inv0 = 1.0f / lrun0;
    float inv1 = 1.0f / lrun1;
    int b  = bh >> 3, hh = bh & 7;
    int qrow0 = qt * 128 + wrow + lg;
    int qrow1 = qrow0 + 8;
    float* h0 = hout + (((size_t)b * SEQ + qrow0) * NHEAD + hh) * DHEAD;
    float* h1 = hout + (((size_t)b * SEQ + qrow1) * NHEAD + hh) * DHEAD;
#pragma unroll
    for (int nt = 0; nt < 8; nt++) {
        int dim = nt * 8 + 2 * lq;
        *(float2*)&h0[dim] = make_float2(oacc[nt][0] * inv0, oacc[nt][1] * inv0);
        *(float2*)&h1[dim] = make_float2(oacc[nt][2] * inv1, oacc[nt][3] * inv1);
    }
}

// ---------------- launcher ----------------
extern "C" void kernel_launch(void* const* d_in, const int* in_sizes, int n_in,
                              void* d_out, int out_size) {
    const float* x  = (const float*)d_in[0];
    const float* Wq = (const float*)d_in[1];
    const float* bq = (const float*)d_in[2];
    const float* Wk = (const float*)d_in[3];
    const float* bk = (const float*)d_in[4];
    const float* Wv = (const float*)d_in[5];
    const float* bv = (const float*)d_in[6];
    const float* Wo = (const float*)d_in[7];
    const float* bo = (const float*)d_in[8];
    const float* W1 = (const float*)d_in[9];
    const float* b1 = (const float*)d_in[10];
    const float* W2 = (const float*)d_in[11];
    const float* b2 = (const float*)d_in[12];
    float* out = (float*)d_out;

    float *z, *q, *k, *v, *h, *z2, *f;
    cudaGetSymbolAddress((void**)&z,  g_z);
    cudaGetSymbolAddress((void**)&q,  g_q);
    cudaGetSymbolAddress((void**)&k,  g_k);
    cudaGetSymbolAddress((void**)&v,  g_v);
    cudaGetSymbolAddress((void**)&h,  g_h);
    cudaGetSymbolAddress((void**)&z2, g_z2);
    cudaGetSymbolAddress((void**)&f,  g_f);

    // attention smem: K(64*68) + V(64*72) + P(128*68) uint32
    const int att_smem_bytes = (64 * KST + 64 * VST + 128 * PST) * 4;  // 70656
    static int configured = 0;
    if (!configured) {
        cudaFuncSetAttribute(attn_tc_kernel,
                             cudaFuncAttributeMaxDynamicSharedMemorySize,
                             att_smem_bytes);
        configured = 1;
    }

    // 1) z = x + pe
    pe_add_kernel<<<(MROWS * DEMB) / 256, 256>>>(x, z);

    // 2) Q, K, V projections with head scatter (tf32 tensor cores)
    dim3 gg(GN / 128, MROWS / 128);   // (4, 64)
    gemm_tc_kernel<0><<<gg, 256>>>(z, Wq, bq, nullptr, q);
    gemm_tc_kernel<0><<<gg, 256>>>(z, Wk, bk, nullptr, k);
    gemm_tc_kernel<0><<<gg, 256>>>(z, Wv, bv, nullptr, v);

    // 3) attention (tensor cores)
    attn_tc_kernel<<<dim3(BATCH * NHEAD, SEQ / 128), 256, att_smem_bytes>>>(q, k, v, h);

    // 4) out projection + residual
    gemm_tc_kernel<1><<<gg, 256>>>(h, Wo, bo, z, z2);

    // 5) FFN
    gemm_tc_kernel<2><<<gg, 256>>>(z2, W1, b1, nullptr, f);
    gemm_tc_kernel<2><<<gg, 256>>>(f,  W2, b2, nullptr, out);
}

// round 4
// speedup vs baseline: 6.4794x; 1.3591x over previous
#include <cuda_runtime.h>
#include <math.h>
#include <stdint.h>

// Problem constants
#define BATCH 4
#define SEQ   2048
#define DEMB  512
#define NHEAD 8
#define DHEAD 64
#define DMODL 512              // NHEAD*DHEAD
#define MROWS (BATCH*SEQ)      // 8192

// ---------------- scratch (device globals; no allocation) ----------------
__device__ float g_z [MROWS * DEMB];   // x + pe
__device__ float g_q [MROWS * DMODL];  // [B,H,S,Dh]
__device__ float g_k [MROWS * DMODL];
__device__ float g_v [MROWS * DMODL];
__device__ float g_h [MROWS * DMODL];  // attention out, [B,S,H*Dh]
__device__ float g_z2[MROWS * DEMB];   // z + h@Wo + bo
__device__ float g_f [MROWS * DEMB];   // leaky(z2@W1+b1)

// ---------------- helpers ----------------
__device__ __forceinline__ uint32_t f2tf32(float x) {
    uint32_t r;
    asm("cvt.rna.tf32.f32 %0, %1;" : "=r"(r) : "f"(x));
    return r;
}

__device__ __forceinline__ void mma_tf32(float c[4],
                                         const uint32_t a[4],
                                         const uint32_t b0, const uint32_t b1) {
    asm volatile(
        "mma.sync.aligned.m16n8k8.row.col.f32.tf32.tf32.f32 "
        "{%0,%1,%2,%3}, {%4,%5,%6,%7}, {%8,%9}, {%0,%1,%2,%3};"
        : "+f"(c[0]), "+f"(c[1]), "+f"(c[2]), "+f"(c[3])
        : "r"(a[0]), "r"(a[1]), "r"(a[2]), "r"(a[3]),
          "r"(b0), "r"(b1));
}

__device__ __forceinline__ void cp_async16(void* dst_smem, const void* src) {
    uint32_t d = (uint32_t)__cvta_generic_to_shared(dst_smem);
    asm volatile("cp.async.ca.shared.global [%0], [%1], 16;" :: "r"(d), "l"(src));
}
#define CP_COMMIT() asm volatile("cp.async.commit_group;")
#define CP_WAIT1()  asm volatile("cp.async.wait_group 1;")

// ---------------- 1) positional encoding add ----------------
__global__ void pe_add_kernel(const float* __restrict__ x, float* __restrict__ z) {
    int idx = blockIdx.x * blockDim.x + threadIdx.x;   // over MROWS*DEMB
    if (idx >= MROWS * DEMB) return;
    int d = idx & (DEMB - 1);
    int s = (idx >> 9) & (SEQ - 1);
    int i2 = (d >> 1) * 2;
    float divv = expf(-(float)i2 * (9.210340371976184f / 512.0f));
    float ang = (float)s * divv;
    float pe = (d & 1) ? cosf(ang) : sinf(ang);
    z[idx] = x[idx] + pe;
}

// ---------------- 2) tf32 tensor-core GEMM, cp.async double-buffered ----------------
// C[M,N] = A[M,K] @ W[K,N] + bias; M=8192, N=512, K=512
// Block tile 128x128, k-chunk 32, 256 threads (8 warps 2x4), warp tile 64x32.
// Smem: A raw fp32 [m][k] stride 36 (conflict-free: lg*4+lq distinct banks)
//       B raw fp32 [k][n] stride 136 (conflict-free: lq*8+lg distinct banks)
// tf32 conversion (RNA) at fragment-load time.
// MODE 0: QKV (blockIdx.z selects W/bias/C, head-scatter epilogue)
// MODE 1: residual add; MODE 2: leaky relu.
#define GK 512
#define GN 512
#define AST 36
#define BST 136
#define GEMM_SMEM_BYTES ((2*128*AST + 2*32*BST) * 4)   // 71680

extern __shared__ float gemm_smem[];

template<int MODE>
__global__ __launch_bounds__(256, 2)
void gemm_tc_kernel(const float* __restrict__ A,
                    const float* __restrict__ Wa, const float* __restrict__ Wb,
                    const float* __restrict__ Wc,
                    const float* __restrict__ ba, const float* __restrict__ bb,
                    const float* __restrict__ bc,
                    const float* __restrict__ resid,
                    float* __restrict__ Ca, float* __restrict__ Cb,
                    float* __restrict__ Cc) {
    const float* W    = Wa;
    const float* bias = ba;
    float*       C    = Ca;
    if (MODE == 0) {
        if (blockIdx.z == 1) { W = Wb; bias = bb; C = Cb; }
        else if (blockIdx.z == 2) { W = Wc; bias = bc; C = Cc; }
    }

    float* Asm = gemm_smem;                 // 2 x 128 x AST
    float* Bsm = gemm_smem + 2 * 128 * AST; // 2 x 32 x BST

    const int bm = blockIdx.y * 128;
    const int bn = blockIdx.x * 128;
    const int tid  = threadIdx.x;
    const int lane = tid & 31;
    const int wid  = tid >> 5;
    const int wm = (wid >> 2) * 64;    // 0 or 64
    const int wn = (wid & 3) * 32;     // 0..96
    const int lq = lane & 3;
    const int lg = lane >> 2;

    float acc[4][4][4];
#pragma unroll
    for (int i = 0; i < 4; i++)
#pragma unroll
        for (int j = 0; j < 4; j++)
#pragma unroll
            for (int r = 0; r < 4; r++) acc[i][j][r] = 0.0f;

    // --- staging lambda-ish macros via explicit code ---
    // A: 128 rows x 32 floats (128B) = 8 x 16B segs/row, 1024 segs, 4/thread
    // B: 32 rows x 128 floats (512B) = 32 x 16B segs/row, 1024 segs, 4/thread
    const int a_row = tid >> 1;              // used with i*? -> recompute inline
    (void)a_row;

#define STAGE_CHUNK(cc, buf)                                                    \
    {                                                                           \
        float* Ad = Asm + (buf) * 128 * AST;                                    \
        float* Bd = Bsm + (buf) * 32 * BST;                                     \
        int k0 = (cc) * 32;                                                     \
        _Pragma("unroll")                                                       \
        for (int i = 0; i < 4; i++) {                                           \
            int idx = tid + i * 256;                                            \
            int row = idx >> 3, seg = idx & 7;                                  \
            cp_async16(&Ad[row * AST + seg * 4],                                \
                       &A[(size_t)(bm + row) * GK + k0 + seg * 4]);             \
        }                                                                       \
        _Pragma("unroll")                                                       \
        for (int i = 0; i < 4; i++) {                                           \
            int idx = tid + i * 256;                                            \
            int row = idx >> 5, seg = idx & 31;                                 \
            cp_async16(&Bd[row * BST + seg * 4],                                \
                       &W[(size_t)(k0 + row) * GN + bn + seg * 4]);             \
        }                                                                       \
    }

    // prologue: chunks 0 and 1 in flight
    STAGE_CHUNK(0, 0); CP_COMMIT();
    STAGE_CHUNK(1, 1); CP_COMMIT();

    for (int c = 0; c < 16; c++) {
        CP_WAIT1();            // chunk c landed
        __syncthreads();

        const float* Abuf = Asm + (c & 1) * 128 * AST;
        const float* Bbuf = Bsm + (c & 1) * 32 * BST;

#pragma unroll
        for (int ks = 0; ks < 32; ks += 8) {
            uint32_t afrag[4][4];
#pragma unroll
            for (int mt = 0; mt < 4; mt++) {
                int row = wm + mt * 16 + lg;
                afrag[mt][0] = f2tf32(Abuf[(row)     * AST + ks + lq]);
                afrag[mt][1] = f2tf32(Abuf[(row + 8) * AST + ks + lq]);
                afrag[mt][2] = f2tf32(Abuf[(row)     * AST + ks + lq + 4]);
                afrag[mt][3] = f2tf32(Abuf[(row + 8) * AST + ks + lq + 4]);
            }
            uint32_t bfrag[4][2];
#pragma unroll
            for (int nt = 0; nt < 4; nt++) {
                int ncol = wn + nt * 8 + lg;
                bfrag[nt][0] = f2tf32(Bbuf[(ks + lq)     * BST + ncol]);
                bfrag[nt][1] = f2tf32(Bbuf[(ks + lq + 4) * BST + ncol]);
            }
#pragma unroll
            for (int mt = 0; mt < 4; mt++)
#pragma unroll
                for (int nt = 0; nt < 4; nt++)
                    mma_tf32(acc[mt][nt], afrag[mt], bfrag[nt][0], bfrag[nt][1]);
        }

        __syncthreads();       // everyone done reading buf (c&1)
        if (c + 2 < 16) { STAGE_CHUNK(c + 2, (c & 1)); }
        CP_COMMIT();           // commit (possibly empty) to keep group count in step
    }
#undef STAGE_CHUNK

    // --- epilogue ---
#pragma unroll
    for (int mt = 0; mt < 4; mt++) {
#pragma unroll
        for (int nt = 0; nt < 4; nt++) {
#pragma unroll
            for (int half = 0; half < 2; half++) {
                int m = bm + wm + mt * 16 + lg + half * 8;
                int n = bn + wn + nt * 8 + 2 * lq;
                float v0 = acc[mt][nt][half * 2 + 0] + bias[n];
                float v1 = acc[mt][nt][half * 2 + 1] + bias[n + 1];
                if (MODE == 0) {
                    int b = m >> 11, s = m & (SEQ - 1);
                    int h = n >> 6,  dh = n & 63;
                    *(float2*)&C[((((size_t)b * NHEAD + h) * SEQ + s) << 6) + dh] =
                        make_float2(v0, v1);
                } else if (MODE == 1) {
                    float2 r = *(const float2*)&resid[(size_t)m * GN + n];
                    *(float2*)&C[(size_t)m * GN + n] = make_float2(v0 + r.x, v1 + r.y);
                } else {
                    float2 val;
                    val.x = (v0 > 0.0f) ? v0 : 0.01f * v0;
                    val.y = (v1 > 0.0f) ? v1 : 0.01f * v1;
                    *(float2*)&C[(size_t)m * GN + n] = val;
                }
            }
        }
    }
}

// ---------------- 3) tensor-core flash attention (tf32) ----------------
#define KST 68
#define VST 72
#define PST 68

extern __shared__ uint32_t att_smem[];

__global__ __launch_bounds__(256)
void attn_tc_kernel(const float* __restrict__ q, const float* __restrict__ k,
                    const float* __restrict__ v, float* __restrict__ hout) {
    uint32_t* Ksh = att_smem;                 // 64*68
    uint32_t* Vsh = Ksh + 64 * KST;           // 64*72
    uint32_t* Psh = Vsh + 64 * VST;           // 128*68 (also Q staging)

    const int bh  = blockIdx.x;               // 0..31
    const int qt  = blockIdx.y;               // 0..15
    const int tid = threadIdx.x;
    const int lane = tid & 31;
    const int wid  = tid >> 5;                 // 0..7
    const int lq = lane & 3;
    const int lg = lane >> 2;
    const int wrow = wid * 16;

    const float* qbase = q + ((size_t)bh * SEQ + qt * 128) * DHEAD;
#pragma unroll
    for (int i = 0; i < 8; i++) {
        int idx = i * 256 + tid;
        int row = idx >> 4;
        int c4  = idx & 15;
        float4 t = *(const float4*)&qbase[row * DHEAD + c4 * 4];
        uint4 u;
        u.x = f2tf32(t.x * 0.125f); u.y = f2tf32(t.y * 0.125f);
        u.z = f2tf32(t.z * 0.125f); u.w = f2tf32(t.w * 0.125f);
        *(uint4*)&Psh[row * PST + c4 * 4] = u;
    }
    __syncthreads();

    uint32_t qfrag[8][4];
#pragma unroll
    for (int kc = 0; kc < 8; kc++) {
        qfrag[kc][0] = Psh[(wrow + lg)     * PST + kc * 8 + lq];
        qfrag[kc][1] = Psh[(wrow + lg + 8) * PST + kc * 8 + lq];
        qfrag[kc][2] = Psh[(wrow + lg)     * PST + kc * 8 + lq + 4];
        qfrag[kc][3] = Psh[(wrow + lg + 8) * PST + kc * 8 + lq + 4];
    }

    float oacc[8][4];
#pragma unroll
    for (int nt = 0; nt < 8; nt++)
#pragma unroll
        for (int r = 0; r < 4; r++) oacc[nt][r] = 0.0f;
    float mrun0 = -1e30f, mrun1 = -1e30f;
    float lrun0 = 0.0f,   lrun1 = 0.0f;

    const float* kb = k + (size_t)bh * SEQ * DHEAD;
    const float* vb = v + (size_t)bh * SEQ * DHEAD;

    for (int kt = 0; kt < SEQ / 64; kt++) {
        __syncthreads();
#pragma unroll
        for (int i = 0; i < 4; i++) {
            int idx = i * 256 + tid;
            int key = idx >> 4;
            int c4  = idx & 15;
            float4 kk = *(const float4*)&kb[(kt * 64 + key) * DHEAD + c4 * 4];
            uint4 uk;
            uk.x = f2tf32(kk.x); uk.y = f2tf32(kk.y);
            uk.z = f2tf32(kk.z); uk.w = f2tf32(kk.w);
            *(uint4*)&Ksh[key * KST + c4 * 4] = uk;
            float4 vv = *(const float4*)&vb[(kt * 64 + key) * DHEAD + c4 * 4];
            uint4 uv;
            uv.x = f2tf32(vv.x); uv.y = f2tf32(vv.y);
            uv.z = f2tf32(vv.z); uv.w = f2tf32(vv.w);
            *(uint4*)&Vsh[key * VST + c4 * 4] = uv;
        }
        __syncthreads();

        float sacc[8][4];
#pragma unroll
        for (int nt = 0; nt < 8; nt++)
#pragma unroll
            for (int r = 0; r < 4; r++) sacc[nt][r] = 0.0f;
#pragma unroll
        for (int kc = 0; kc < 8; kc++) {
#pragma unroll
            for (int nt = 0; nt < 8; nt++) {
                uint32_t b0 = Ksh[(nt * 8 + lg) * KST + kc * 8 + lq];
                uint32_t b1 = Ksh[(nt * 8 + lg) * KST + kc * 8 + lq + 4];
                mma_tf32(sacc[nt], qfrag[kc], b0, b1);
            }
        }

        float tmax0 = mrun0, tmax1 = mrun1;
#pragma unroll
        for (int nt = 0; nt < 8; nt++) {
            tmax0 = fmaxf(tmax0, fmaxf(sacc[nt][0], sacc[nt][1]));
            tmax1 = fmaxf(tmax1, fmaxf(sacc[nt][2], sacc[nt][3]));
        }
        tmax0 = fmaxf(tmax0, __shfl_xor_sync(0xffffffff, tmax0, 1));
        tmax0 = fmaxf(tmax0, __shfl_xor_sync(0xffffffff, tmax0, 2));
        tmax1 = fmaxf(tmax1, __shfl_xor_sync(0xffffffff, tmax1, 1));
        tmax1 = fmaxf(tmax1, __shfl_xor_sync(0xffffffff, tmax1, 2));

        float corr0 = __expf(mrun0 - tmax0);
        float corr1 = __expf(mrun1 - tmax1);
        mrun0 = tmax0; mrun1 = tmax1;
#pragma unroll
        for (int nt = 0; nt < 8; nt++) {
            oacc[nt][0] *= corr0; oacc[nt][1] *= corr0;
            oacc[nt][2] *= corr1; oacc[nt][3] *= corr1;
        }

        float ps0 = 0.0f, ps1 = 0.0f;
#pragma unroll
        for (int nt = 0; nt < 8; nt++) {
            float p0 = __expf(sacc[nt][0] - mrun0);
            float p1 = __expf(sacc[nt][1] - mrun0);
            float p2 = __expf(sacc[nt][2] - mrun1);
            float p3 = __expf(sacc[nt][3] - mrun1);
            ps0 += p0 + p1;
            ps1 += p2 + p3;
            int col = nt * 8 + 2 * lq;
            Psh[(wrow + lg)     * PST + col]     = f2tf32(p0);
            Psh[(wrow + lg)     * PST + col + 1] = f2tf32(p1);
            Psh[(wrow + lg + 8) * PST + col]     = f2tf32(p2);
            Psh[(wrow + lg + 8) * PST + col + 1] = f2tf32(p3);
        }
        ps0 += __shfl_xor_sync(0xffffffff, ps0, 1);
        ps0 += __shfl_xor_sync(0xffffffff, ps0, 2);
        ps1 += __shfl_xor_sync(0xffffffff, ps1, 1);
        ps1 += __shfl_xor_sync(0xffffffff, ps1, 2);
        lrun0 = lrun0 * corr0 + ps0;
        lrun1 = lrun1 * corr1 + ps1;

        __syncwarp();

#pragma unroll
        for (int kc = 0; kc < 8; kc++) {
            uint32_t a[4];
            a[0] = Psh[(wrow + lg)     * PST + kc * 8 + lq];
            a[1] = Psh[(wrow + lg + 8) * PST + kc * 8 + lq];
            a[2] = Psh[(wrow + lg)     * PST + kc * 8 + lq + 4];
            a[3] = Psh[(wrow + lg + 8) * PST + kc * 8 + lq + 4];
#pragma unroll
            for (int nt = 0; nt < 8; nt++) {
                uint32_t b0 = Vsh[(kc * 8 + lq)     * VST + nt * 8 + lg];
                uint32_t b1 = Vsh[(kc * 8 + lq + 4) * VST + nt * 8 + lg];
                mma_tf32(oacc[nt], a, b0, b1);
            }
        }
        __syncwarp();
    }

    float inv0 = 1.0f / lrun0;
    float inv1 = 1.0f / lrun1;
    int b  = bh >> 3, hh = bh & 7;
    int qrow0 = qt * 128 + wrow + lg;
    int qrow1 = qrow0 + 8;
    float* h0 = hout + (((size_t)b * SEQ + qrow0) * NHEAD + hh) * DHEAD;
    float* h1 = hout + (((size_t)b * SEQ + qrow1) * NHEAD + hh) * DHEAD;
#pragma unroll
    for (int nt = 0; nt < 8; nt++) {
        int dim = nt * 8 + 2 * lq;
        *(float2*)&h0[dim] = make_float2(oacc[nt][0] * inv0, oacc[nt][1] * inv0);
        *(float2*)&h1[dim] = make_float2(oacc[nt][2] * inv1, oacc[nt][3] * inv1);
    }
}

// ---------------- launcher ----------------
extern "C" void kernel_launch(void* const* d_in, const int* in_sizes, int n_in,
                              void* d_out, int out_size) {
    const float* x  = (const float*)d_in[0];
    const float* Wq = (const float*)d_in[1];
    const float* bq = (const float*)d_in[2];
    const float* Wk = (const float*)d_in[3];
    const float* bk = (const float*)d_in[4];
    const float* Wv = (const float*)d_in[5];
    const float* bv = (const float*)d_in[6];
    const float* Wo = (const float*)d_in[7];
    const float* bo = (const float*)d_in[8];
    const float* W1 = (const float*)d_in[9];
    const float* b1 = (const float*)d_in[10];
    const float* W2 = (const float*)d_in[11];
    const float* b2 = (const float*)d_in[12];
    float* out = (float*)d_out;

    float *z, *q, *k, *v, *h, *z2, *f;
    cudaGetSymbolAddress((void**)&z,  g_z);
    cudaGetSymbolAddress((void**)&q,  g_q);
    cudaGetSymbolAddress((void**)&k,  g_k);
    cudaGetSymbolAddress((void**)&v,  g_v);
    cudaGetSymbolAddress((void**)&h,  g_h);
    cudaGetSymbolAddress((void**)&z2, g_z2);
    cudaGetSymbolAddress((void**)&f,  g_f);

    const int att_smem_bytes = (64 * KST + 64 * VST + 128 * PST) * 4;  // 70656
    static int configured = 0;
    if (!configured) {
        cudaFuncSetAttribute(attn_tc_kernel,
                             cudaFuncAttributeMaxDynamicSharedMemorySize,
                             att_smem_bytes);
        cudaFuncSetAttribute(gemm_tc_kernel<0>,
                             cudaFuncAttributeMaxDynamicSharedMemorySize,
                             GEMM_SMEM_BYTES);
        cudaFuncSetAttribute(gemm_tc_kernel<1>,
                             cudaFuncAttributeMaxDynamicSharedMemorySize,
                             GEMM_SMEM_BYTES);
        cudaFuncSetAttribute(gemm_tc_kernel<2>,
                             cudaFuncAttributeMaxDynamicSharedMemorySize,
                             GEMM_SMEM_BYTES);
        configured = 1;
    }

    // 1) z = x + pe
    pe_add_kernel<<<(MROWS * DEMB) / 256, 256>>>(x, z);

    // 2) fused QKV projection (blockIdx.z picks Wq/Wk/Wv), head-scatter epilogue
    dim3 gqkv(GN / 128, MROWS / 128, 3);   // (4, 64, 3)
    gemm_tc_kernel<0><<<gqkv, 256, GEMM_SMEM_BYTES>>>(
        z, Wq, Wk, Wv, bq, bk, bv, nullptr, q, k, v);

    // 3) attention (tensor cores)
    attn_tc_kernel<<<dim3(BATCH * NHEAD, SEQ / 128), 256, att_smem_bytes>>>(q, k, v, h);

    // 4) out projection + residual
    dim3 gg(GN / 128, MROWS / 128, 1);
    gemm_tc_kernel<1><<<gg, 256, GEMM_SMEM_BYTES>>>(
        h, Wo, nullptr, nullptr, bo, nullptr, nullptr, z, z2, nullptr, nullptr);

    // 5) FFN
    gemm_tc_kernel<2><<<gg, 256, GEMM_SMEM_BYTES>>>(
        z2, W1, nullptr, nullptr, b1, nullptr, nullptr, nullptr, f, nullptr, nullptr);
    gemm_tc_kernel<2><<<gg, 256, GEMM_SMEM_BYTES>>>(
        f, W2, nullptr, nullptr, b2, nullptr, nullptr, nullptr, out, nullptr, nullptr);
}